// round 16
// baseline (speedup 1.0000x reference)
#include <cuda_runtime.h>
#include <cuda_fp16.h>
#include <math.h>
#include <stdint.h>

#define B_ROWS 2048
#define D_DIM  512
#define W_DIM  512
#define N_LEAF 64
#define N_NODE 63
#define P_N    8
#define K_TOT  (P_N * D_DIM)     // 4096
#define N_KT   (K_TOT / 64)      // 64 kc64 tiles
#define NIT    32                // 8 i-chunks x 4 p-pairs

// ---------------------------------------------------------------------------
// Device scratch (no cudaMalloc allowed).  min/max are statically initialized
// and idempotent across graph replays (same inputs -> same extrema).
// ---------------------------------------------------------------------------
__device__ float  g_theta[B_ROWS];
__device__ int    g_tmin_i = 0x7f800000;
__device__ int    g_tmax_i = 0;
__device__ int    g_count  = 0;
__device__ float  g_Dn[P_N * N_LEAF];                        // d_l at nodes
__device__ __half g_Up[(size_t)(W_DIM / 64) * N_KT * 4096];  // U granules

// Chebyshev-1 nodes (P=8) on [-1,1] and barycentric weights (canonical)
__device__ __constant__ float c_tp[P_N] = {
    0.98078528f,  0.83146961f,  0.55557023f,  0.19509032f,
   -0.19509032f, -0.55557023f, -0.83146961f, -0.98078528f };
__device__ __constant__ float c_wp[P_N] = {
    0.19509032f, -0.55557023f,  0.83146961f, -0.98078528f,
    0.98078528f, -0.83146961f,  0.55557023f, -0.19509032f };

// ---------------------------------------------------------------------------
// Helpers
// ---------------------------------------------------------------------------
__device__ __forceinline__ uint32_t smem_u32(const void* p) {
    uint32_t a;
    asm("{ .reg .u64 t; cvta.to.shared.u64 t, %1; cvt.u32.u64 %0, t; }"
        : "=r"(a) : "l"(p));
    return a;
}

__device__ __forceinline__ float sigmoidf_(float z) { return 1.0f / (1.0f + expf(-z)); }

__device__ __forceinline__ void mma_f16(float c[4], const uint32_t a[4], const uint32_t b[2]) {
    asm volatile("mma.sync.aligned.m16n8k16.row.col.f32.f16.f16.f32 "
                 "{%0,%1,%2,%3}, {%4,%5,%6,%7}, {%8,%9}, {%0,%1,%2,%3};"
                 : "+f"(c[0]), "+f"(c[1]), "+f"(c[2]), "+f"(c[3])
                 : "r"(a[0]), "r"(a[1]), "r"(a[2]), "r"(a[3]), "r"(b[0]), "r"(b[1]));
}

__device__ __forceinline__ uint32_t pack_h2(float a, float b) {
    __half2 t = __floats2half2_rn(a, b);
    return *reinterpret_cast<uint32_t*>(&t);
}

#define CP_ASYNC16(dst, src) \
    asm volatile("cp.async.cg.shared.global [%0], [%1], 16;" :: "r"(dst), "l"(src))
#define CP_COMMIT() asm volatile("cp.async.commit_group;" ::: "memory")
#define CP_WAIT1()  asm volatile("cp.async.wait_group 1;" ::: "memory")

// ---------------------------------------------------------------------------
// Kernel 1: theta per row (one warp per row) + global min/max + (last block)
// evaluates the leaf distribution at the P_N Chebyshev nodes.
// ---------------------------------------------------------------------------
__global__ void __launch_bounds__(256) theta_kernel(
    const float* __restrict__ x, const float* __restrict__ ray,
    const float* __restrict__ w_i, const float* __restrict__ b_i,
    const float* __restrict__ a_i, const int* __restrict__ idx)
{
    __shared__ float sray[D_DIM];
    __shared__ int slast;
    const int tid = threadIdx.x;
    for (int i = tid; i < D_DIM; i += 256) sray[i] = ray[i];
    __syncthreads();

    const int warp = tid >> 5;
    const int lane = tid & 31;
    const int row  = blockIdx.x * 8 + warp;

    const float* xr = x + (size_t)row * D_DIM;
    float dot = 0.f, ss = 0.f, rss = 0.f;
#pragma unroll
    for (int j = 0; j < 4; j++) {
        float4 xv = reinterpret_cast<const float4*>(xr)[lane + 32 * j];
        float4 rv = reinterpret_cast<const float4*>(sray)[lane + 32 * j];
        dot += xv.x * rv.x + xv.y * rv.y + xv.z * rv.z + xv.w * rv.w;
        ss  += xv.x * xv.x + xv.y * xv.y + xv.z * xv.z + xv.w * xv.w;
        rss += rv.x * rv.x + rv.y * rv.y + rv.z * rv.z + rv.w * rv.w;
    }
#pragma unroll
    for (int o = 16; o > 0; o >>= 1) {
        dot += __shfl_xor_sync(0xffffffffu, dot, o);
        ss  += __shfl_xor_sync(0xffffffffu, ss,  o);
        rss += __shfl_xor_sync(0xffffffffu, rss, o);
    }
    float xn = fmaxf(sqrtf(ss),  1e-8f);
    float rn = fmaxf(sqrtf(rss), 1e-8f);
    float c  = dot / (xn * rn);
    c = fminf(fmaxf(c, -1.0f), 1.0f);
    const float angle = acosf(c) * 0.3183098861837907f;

    if (lane == 0) {
        g_theta[row] = angle;
        atomicMin(&g_tmin_i, __float_as_int(angle));
        atomicMax(&g_tmax_i, __float_as_int(angle));
    }

    // grid-completion: last block evaluates the tree at the Chebyshev nodes
    __syncthreads();
    if (tid == 0) {
        __threadfence();
        slast = (atomicAdd(&g_count, 1) == (int)gridDim.x - 1) ? 1 : 0;
    }
    __syncthreads();
    if (slast) {
        if (tid == 0) g_count = 0;     // reset for next replay (idempotent)
        __threadfence();
        if (tid < P_N) {
            const int p = tid;
            float tmin = __int_as_float(*(volatile int*)&g_tmin_i);
            float tmax = __int_as_float(*(volatile int*)&g_tmax_i);
            float c0 = 0.5f * (tmin + tmax);
            float hh = 0.5f * (tmax - tmin) + 1e-6f;
            float th = c0 + hh * c_tp[p];
            float dec[N_NODE];
            for (int n = 0; n < N_NODE; n++) {
                float nf = (0.5f + sigmoidf_(w_i[n])) * th - sigmoidf_(b_i[n]);
                dec[n] = sigmoidf_(nf * (1.0f + a_i[n]));
            }
            for (int l = 0; l < N_LEAF; l++) {
                float pr = 1.0f;
                for (int t = 0; t < 6; t++) {
                    int j = idx[l * 6 + t];
                    float v = (j < N_NODE) ? dec[j] : (1.0f - dec[j - N_NODE]);
                    pr *= v;
                }
                g_Dn[p * N_LEAF + l] = pr;
            }
        }
    }
}

// ---------------------------------------------------------------------------
// Kernel 2: fused U-build + granule permute.
// Block = (ic: 64-i chunk, sw: 16-w slice); grid (8, 32) = 256 blocks.
// Computes U[p][i][w] = sum_l Dn[p][l] * T[l][i][w] for its (64i x 16w) tile,
// all 8 p at once (T read exactly once), stages fp16 in smem, emits granule
// rows of g_Up in exactly the layout gemm's issue_b2 consumes.
// ---------------------------------------------------------------------------
__global__ void __launch_bounds__(256, 4) ubuild_kernel(const float* __restrict__ T) {
    __shared__ float sDn[P_N * N_LEAF];
    __shared__ unsigned short su[P_N][64][17];   // fp16 bits, padded

    const int tid = threadIdx.x;
    const int ic = blockIdx.x;       // 0..7
    const int sw = blockIdx.y;       // 0..31
    const int nb64 = sw >> 2, ws = sw & 3;

    for (int e = tid; e < P_N * N_LEAF; e += 256) sDn[e] = g_Dn[e];
    __syncthreads();

    const int w    = tid & 15;       // w within slice
    const int isub = tid >> 4;       // 0..15; thread owns i = isub + 16*r

    float acc[P_N][4];
#pragma unroll
    for (int p = 0; p < P_N; p++)
#pragma unroll
        for (int r = 0; r < 4; r++) acc[p][r] = 0.f;

    const float* base = T + (size_t)(ic * 64 + isub) * W_DIM + sw * 16 + w;
#pragma unroll 2
    for (int l = 0; l < N_LEAF; l++) {
        const float* bl = base + (size_t)l * (D_DIM * W_DIM);
        float t0 = bl[0];
        float t1 = bl[16 * W_DIM];
        float t2 = bl[32 * W_DIM];
        float t3 = bl[48 * W_DIM];
#pragma unroll
        for (int p = 0; p < P_N; p++) {
            float s = sDn[p * N_LEAF + l];
            acc[p][0] = fmaf(s, t0, acc[p][0]);
            acc[p][1] = fmaf(s, t1, acc[p][1]);
            acc[p][2] = fmaf(s, t2, acc[p][2]);
            acc[p][3] = fmaf(s, t3, acc[p][3]);
        }
    }

#pragma unroll
    for (int p = 0; p < P_N; p++)
#pragma unroll
        for (int r = 0; r < 4; r++)
            su[p][isub + 16 * r][w] = __half_as_ushort(__float2half_rn(acc[p][r]));
    __syncthreads();

    // Emit 1024 granules (4 per thread): kt = p*8+ic, row = (ws*4+ks)*32+ln
#pragma unroll
    for (int e = 0; e < 4; e++) {
        int gid = tid + e * 256;
        int p  = gid >> 7, f = gid & 127;
        int ks = f >> 5,  ln = f & 31;
        int g = ln >> 2,  tg = ln & 3;
        int k0 = ks * 16 + 2 * tg;
        int n0 = g, n1 = g + 8;
        uint4 u;
        u.x = (uint32_t)su[p][k0][n0]     | ((uint32_t)su[p][k0 + 1][n0] << 16);
        u.y = (uint32_t)su[p][k0 + 8][n0] | ((uint32_t)su[p][k0 + 9][n0] << 16);
        u.z = (uint32_t)su[p][k0][n1]     | ((uint32_t)su[p][k0 + 1][n1] << 16);
        u.w = (uint32_t)su[p][k0 + 8][n1] | ((uint32_t)su[p][k0 + 9][n1] << 16);
        __half* dst = g_Up + ((size_t)nb64 * N_KT + p * 8 + ic) * 4096
                      + ((size_t)(ws * 4 + ks) * 32 + ln) * 8;
        *reinterpret_cast<uint4*>(dst) = u;
    }
}

// ---------------------------------------------------------------------------
// Kernel 3: GEMM with on-the-fly A.  out[b,w] = sum_p cf[b,p] (x_b . U_p)[w].
// CTA 128m x 32n, 256 thr = 8 warps (4m x 2n), warp tile 32m x 16n.
// NIT=32: each iteration stages an 8KB B tile holding p = 2*pp and 2*pp+1
// (one wait+sync per 32 HMMA), then two 16-HMMA + cf-epilogue sub-steps.
// ---------------------------------------------------------------------------
// smem: XW [128 rows][36 words] @0 (18432) | B 3x8192 @18432 | CF @43008
#define XWOFF  0
#define BOFF   18432
#define CFOFF  43008
#define SMEM_BYTES (43008 + 4096)

__device__ __forceinline__ void issue_b2(uint32_t sb, int buf, int pbase, int ic,
                                         int nb64, int h, int tid) {
    const int ws2 = tid >> 7, ks = (tid >> 5) & 3, ln = tid & 31;
    const uint32_t off_in  = ((2 * h + ws2) * 4 + ks) * 512 + ln * 16;
    const uint32_t off_out = (ws2 * 4 + ks) * 512 + ln * 16;
#pragma unroll
    for (int q = 0; q < 2; q++) {
        const char* src = (const char*)(g_Up +
            ((size_t)nb64 * N_KT + (pbase + q) * 8 + ic) * 4096) + off_in;
        uint32_t dst = sb + BOFF + buf * 8192 + q * 4096 + off_out;
        CP_ASYNC16(dst, src);
    }
}

__global__ void __launch_bounds__(256, 2) gemm_kernel(
    const float* __restrict__ x, float* __restrict__ out)
{
    extern __shared__ char sm[];
    const uint32_t sb = smem_u32(sm);
    const int tid  = threadIdx.x;
    const int wid  = tid >> 5;
    const int lane = tid & 31;
    const int wm   = wid & 3;
    const int wn   = wid >> 2;
    const int g    = lane >> 2;
    const int tg   = lane & 3;
    const int nb32 = blockIdx.x;
    const int nb64 = nb32 >> 1;
    const int h    = nb32 & 1;
    const int mb = blockIdx.y;
    const int m0 = mb * 128;

    uint32_t* XW = reinterpret_cast<uint32_t*>(sm + XWOFF);
    float*    CF = reinterpret_cast<float*>(sm + CFOFF);

    if (tid < 128) {
        float tmin = __int_as_float(g_tmin_i);
        float tmax = __int_as_float(g_tmax_i);
        float c0 = 0.5f * (tmin + tmax);
        float hh = 0.5f * (tmax - tmin) + 1e-6f;
        float t = (g_theta[m0 + tid] - c0) / hh;
        float num[P_N];
        float S = 0.f;
        int hit = -1;
#pragma unroll
        for (int p = 0; p < P_N; p++) {
            float d = t - c_tp[p];
            if (fabsf(d) < 1e-7f) hit = p;
            num[p] = c_wp[p] / d;
            S += num[p];
        }
        if (hit >= 0) {
#pragma unroll
            for (int p = 0; p < P_N; p++) CF[tid * P_N + p] = (p == hit) ? 1.f : 0.f;
        } else {
            float inv = 1.f / S;
#pragma unroll
            for (int p = 0; p < P_N; p++) CF[tid * P_N + p] = num[p] * inv;
        }
    }

    float O[2][2][4];
#pragma unroll
    for (int i = 0; i < 2; i++)
#pragma unroll
        for (int j = 0; j < 2; j++)
#pragma unroll
            for (int r = 0; r < 4; r++) O[i][j][r] = 0.f;

    issue_b2(sb, 0, 0, 0, nb64, h, tid);
    CP_COMMIT();
    issue_b2(sb, 1, 2, 0, nb64, h, tid);
    CP_COMMIT();

    uint32_t A[4][2][4];

    for (int it = 0; it < NIT; it++) {
        const int pp = it & 3;

        CP_WAIT1();
        __syncthreads();

        if (pp == 0) {
            const float* xp = x + (size_t)m0 * D_DIM + (it >> 2) * 64;
#pragma unroll
            for (int e = 0; e < 8; e++) {
                int id = tid + e * 256;
                int m = id >> 4, q = id & 15;
                float4 v = *reinterpret_cast<const float4*>(xp + (size_t)m * D_DIM + q * 4);
                uint2 u = make_uint2(pack_h2(v.x, v.y), pack_h2(v.z, v.w));
                *reinterpret_cast<uint2*>(XW + m * 36 + q * 2) = u;
            }
            __syncthreads();
#pragma unroll
            for (int ks = 0; ks < 4; ks++) {
#pragma unroll
                for (int i = 0; i < 2; i++) {
                    int m = wm * 32 + i * 16 + g;
                    int k = ks * 8 + tg;
                    A[ks][i][0] = XW[m * 36 + k];
                    A[ks][i][1] = XW[(m + 8) * 36 + k];
                    A[ks][i][2] = XW[m * 36 + k + 4];
                    A[ks][i][3] = XW[(m + 8) * 36 + k + 4];
                }
            }
        }

        if (it + 2 < NIT)
            issue_b2(sb, (it + 2) % 3, 2 * ((it + 2) & 3), (it + 2) >> 2, nb64, h, tid);
        CP_COMMIT();

#pragma unroll
        for (int q = 0; q < 2; q++) {
            const int p = 2 * pp + q;
            const char* Bb = sm + BOFF + (it % 3) * 8192 + q * 4096
                             + wn * 2048 + lane * 16;

            float P[2][2][4];
#pragma unroll
            for (int i = 0; i < 2; i++)
#pragma unroll
                for (int j = 0; j < 2; j++)
#pragma unroll
                    for (int r = 0; r < 4; r++) P[i][j][r] = 0.f;

#pragma unroll
            for (int ks = 0; ks < 4; ks++) {
                uint4 bv = *reinterpret_cast<const uint4*>(Bb + ks * 512);
                uint32_t b[2][2];
                b[0][0] = bv.x; b[0][1] = bv.y;
                b[1][0] = bv.z; b[1][1] = bv.w;
#pragma unroll
                for (int i = 0; i < 2; i++)
#pragma unroll
                    for (int j = 0; j < 2; j++)
                        mma_f16(P[i][j], A[ks][i], b[j]);
            }

#pragma unroll
            for (int i = 0; i < 2; i++) {
                int r0 = wm * 32 + i * 16 + g;
                float d0 = CF[r0 * P_N + p];
                float d1 = CF[(r0 + 8) * P_N + p];
#pragma unroll
                for (int j = 0; j < 2; j++) {
                    O[i][j][0] = fmaf(d0, P[i][j][0], O[i][j][0]);
                    O[i][j][1] = fmaf(d0, P[i][j][1], O[i][j][1]);
                    O[i][j][2] = fmaf(d1, P[i][j][2], O[i][j][2]);
                    O[i][j][3] = fmaf(d1, P[i][j][3], O[i][j][3]);
                }
            }
        }
    }

#pragma unroll
    for (int i = 0; i < 2; i++) {
        int r0 = m0 + wm * 32 + i * 16 + g;
#pragma unroll
        for (int j = 0; j < 2; j++) {
            int col = nb32 * 32 + wn * 16 + j * 8 + 2 * tg;
            float2 v0 = make_float2(O[i][j][0], O[i][j][1]);
            float2 v1 = make_float2(O[i][j][2], O[i][j][3]);
            *reinterpret_cast<float2*>(out + (size_t)r0 * W_DIM + col)       = v0;
            *reinterpret_cast<float2*>(out + (size_t)(r0 + 8) * W_DIM + col) = v1;
        }
    }
}

// ---------------------------------------------------------------------------
extern "C" void kernel_launch(void* const* d_in, const int* in_sizes, int n_in,
                              void* d_out, int out_size)
{
    const float* x   = (const float*)d_in[0];
    const float* ray = (const float*)d_in[1];
    const float* w_i = (const float*)d_in[2];
    const float* b_i = (const float*)d_in[3];
    const float* a_i = (const float*)d_in[4];
    const float* T   = (const float*)d_in[5];
    const int*   idx = (const int*)d_in[6];
    float* out = (float*)d_out;

    cudaFuncSetAttribute(gemm_kernel,
                         cudaFuncAttributeMaxDynamicSharedMemorySize, SMEM_BYTES);

    theta_kernel<<<B_ROWS / 8, 256>>>(x, ray, w_i, b_i, a_i, idx);
    ubuild_kernel<<<dim3(8, 32), 256>>>(T);
    gemm_kernel<<<dim3(16, 16), 256, SMEM_BYTES>>>(x, out);
}

// round 17
// speedup vs baseline: 1.4455x; 1.4455x over previous
#include <cuda_runtime.h>
#include <cuda_fp16.h>
#include <math.h>
#include <stdint.h>

#define B_ROWS 2048
#define D_DIM  512
#define W_DIM  512
#define N_LEAF 64
#define N_NODE 63
#define P_N    8
#define K_TOT  (P_N * D_DIM)     // 4096
#define N_KT   (K_TOT / 64)      // 64 kc64 tiles
#define NIT    32                // 8 i-chunks x 4 p-pairs

// ---------------------------------------------------------------------------
// Device scratch (no cudaMalloc allowed).  min/max are statically initialized
// and idempotent across graph replays (same inputs -> same extrema).
// ---------------------------------------------------------------------------
__device__ float  g_theta[B_ROWS];
__device__ int    g_tmin_i = 0x7f800000;
__device__ int    g_tmax_i = 0;
__device__ int    g_count  = 0;
__device__ float  g_Dn[P_N * N_LEAF];                        // d_l at nodes
__device__ __half g_Up[(size_t)(W_DIM / 64) * N_KT * 4096];  // U granules

// Chebyshev-1 nodes (P=8) on [-1,1] and barycentric weights (canonical)
__device__ __constant__ float c_tp[P_N] = {
    0.98078528f,  0.83146961f,  0.55557023f,  0.19509032f,
   -0.19509032f, -0.55557023f, -0.83146961f, -0.98078528f };
__device__ __constant__ float c_wp[P_N] = {
    0.19509032f, -0.55557023f,  0.83146961f, -0.98078528f,
    0.98078528f, -0.83146961f,  0.55557023f, -0.19509032f };

// ---------------------------------------------------------------------------
// Helpers
// ---------------------------------------------------------------------------
__device__ __forceinline__ uint32_t smem_u32(const void* p) {
    uint32_t a;
    asm("{ .reg .u64 t; cvta.to.shared.u64 t, %1; cvt.u32.u64 %0, t; }"
        : "=r"(a) : "l"(p));
    return a;
}

__device__ __forceinline__ float sigmoidf_(float z) { return 1.0f / (1.0f + expf(-z)); }

__device__ __forceinline__ void mma_f16(float c[4], const uint32_t a[4], const uint32_t b[2]) {
    asm volatile("mma.sync.aligned.m16n8k16.row.col.f32.f16.f16.f32 "
                 "{%0,%1,%2,%3}, {%4,%5,%6,%7}, {%8,%9}, {%0,%1,%2,%3};"
                 : "+f"(c[0]), "+f"(c[1]), "+f"(c[2]), "+f"(c[3])
                 : "r"(a[0]), "r"(a[1]), "r"(a[2]), "r"(a[3]), "r"(b[0]), "r"(b[1]));
}

__device__ __forceinline__ uint32_t pack_h2(float a, float b) {
    __half2 t = __floats2half2_rn(a, b);
    return *reinterpret_cast<uint32_t*>(&t);
}

#define CP_ASYNC16(dst, src) \
    asm volatile("cp.async.cg.shared.global [%0], [%1], 16;" :: "r"(dst), "l"(src))
#define CP_COMMIT() asm volatile("cp.async.commit_group;" ::: "memory")
#define CP_WAIT1()  asm volatile("cp.async.wait_group 1;" ::: "memory")

// ---------------------------------------------------------------------------
// Kernel 1: theta per row (one warp per row) + global min/max + (last block)
// PARALLEL evaluation of the leaf distribution at the P_N Chebyshev nodes.
// ---------------------------------------------------------------------------
__global__ void __launch_bounds__(256) theta_kernel(
    const float* __restrict__ x, const float* __restrict__ ray,
    const float* __restrict__ w_i, const float* __restrict__ b_i,
    const float* __restrict__ a_i, const int* __restrict__ idx)
{
    __shared__ float sray[D_DIM];
    __shared__ int slast;
    const int tid = threadIdx.x;
    for (int i = tid; i < D_DIM; i += 256) sray[i] = ray[i];
    __syncthreads();

    const int warp = tid >> 5;
    const int lane = tid & 31;
    const int row  = blockIdx.x * 8 + warp;

    const float* xr = x + (size_t)row * D_DIM;
    float dot = 0.f, ss = 0.f, rss = 0.f;
#pragma unroll
    for (int j = 0; j < 4; j++) {
        float4 xv = reinterpret_cast<const float4*>(xr)[lane + 32 * j];
        float4 rv = reinterpret_cast<const float4*>(sray)[lane + 32 * j];
        dot += xv.x * rv.x + xv.y * rv.y + xv.z * rv.z + xv.w * rv.w;
        ss  += xv.x * xv.x + xv.y * xv.y + xv.z * xv.z + xv.w * xv.w;
        rss += rv.x * rv.x + rv.y * rv.y + rv.z * rv.z + rv.w * rv.w;
    }
#pragma unroll
    for (int o = 16; o > 0; o >>= 1) {
        dot += __shfl_xor_sync(0xffffffffu, dot, o);
        ss  += __shfl_xor_sync(0xffffffffu, ss,  o);
        rss += __shfl_xor_sync(0xffffffffu, rss, o);
    }
    float xn = fmaxf(sqrtf(ss),  1e-8f);
    float rn = fmaxf(sqrtf(rss), 1e-8f);
    float c  = dot / (xn * rn);
    c = fminf(fmaxf(c, -1.0f), 1.0f);
    const float angle = acosf(c) * 0.3183098861837907f;

    if (lane == 0) {
        g_theta[row] = angle;
        atomicMin(&g_tmin_i, __float_as_int(angle));
        atomicMax(&g_tmax_i, __float_as_int(angle));
    }

    // grid-completion: last block evaluates the tree at the Chebyshev nodes
    __syncthreads();
    if (tid == 0) {
        __threadfence();
        slast = (atomicAdd(&g_count, 1) == (int)gridDim.x - 1) ? 1 : 0;
    }
    __syncthreads();
    if (!slast) return;

    // ---- last block only: parallel node-tree evaluation via smem ----
    __shared__ float sdec[P_N][N_LEAF];       // decisions (63 used per p)
    __shared__ int   sidx[N_LEAF * 6];
    __shared__ float sc0, shh;

    if (tid == 0) {
        g_count = 0;                          // reset for next replay
        __threadfence();
        float tmin = __int_as_float(*(volatile int*)&g_tmin_i);
        float tmax = __int_as_float(*(volatile int*)&g_tmax_i);
        sc0 = 0.5f * (tmin + tmax);
        shh = 0.5f * (tmax - tmin) + 1e-6f;
    }
    for (int e = tid; e < N_LEAF * 6; e += 256) sidx[e] = idx[e];
    __syncthreads();

    // decisions: 8p x 63n = 504 entries, 2 per thread
    for (int e = tid; e < P_N * N_NODE; e += 256) {
        int p = e / N_NODE, n = e % N_NODE;
        float th = sc0 + shh * c_tp[p];
        float nf = (0.5f + sigmoidf_(w_i[n])) * th - sigmoidf_(b_i[n]);
        sdec[p][n] = sigmoidf_(nf * (1.0f + a_i[n]));
    }
    __syncthreads();

    // leaves: 8p x 64l = 512 products, 2 per thread
    for (int e = tid; e < P_N * N_LEAF; e += 256) {
        int p = e >> 6, l = e & 63;
        float pr = 1.0f;
#pragma unroll
        for (int t = 0; t < 6; t++) {
            int j = sidx[l * 6 + t];
            float v = (j < N_NODE) ? sdec[p][j] : (1.0f - sdec[p][j - N_NODE]);
            pr *= v;
        }
        g_Dn[p * N_LEAF + l] = pr;
    }
}

// ---------------------------------------------------------------------------
// Kernel 2: fused U-build + granule permute.
// Block = (ic: 64-i chunk, sw: 16-w slice); grid (8, 32) = 256 blocks.
// Computes U[p][i][w] = sum_l Dn[p][l] * T[l][i][w] for its (64i x 16w) tile,
// all 8 p at once (T read exactly once), stages fp16 in smem, emits granule
// rows of g_Up in exactly the layout gemm's issue_b2 consumes.
// ---------------------------------------------------------------------------
__global__ void __launch_bounds__(256, 4) ubuild_kernel(const float* __restrict__ T) {
    __shared__ float sDn[P_N * N_LEAF];
    __shared__ unsigned short su[P_N][64][17];   // fp16 bits, padded

    const int tid = threadIdx.x;
    const int ic = blockIdx.x;       // 0..7
    const int sw = blockIdx.y;       // 0..31
    const int nb64 = sw >> 2, ws = sw & 3;

    for (int e = tid; e < P_N * N_LEAF; e += 256) sDn[e] = g_Dn[e];
    __syncthreads();

    const int w    = tid & 15;       // w within slice
    const int isub = tid >> 4;       // 0..15; thread owns i = isub + 16*r

    float acc[P_N][4];
#pragma unroll
    for (int p = 0; p < P_N; p++)
#pragma unroll
        for (int r = 0; r < 4; r++) acc[p][r] = 0.f;

    const float* base = T + (size_t)(ic * 64 + isub) * W_DIM + sw * 16 + w;
#pragma unroll 2
    for (int l = 0; l < N_LEAF; l++) {
        const float* bl = base + (size_t)l * (D_DIM * W_DIM);
        float t0 = bl[0];
        float t1 = bl[16 * W_DIM];
        float t2 = bl[32 * W_DIM];
        float t3 = bl[48 * W_DIM];
#pragma unroll
        for (int p = 0; p < P_N; p++) {
            float s = sDn[p * N_LEAF + l];
            acc[p][0] = fmaf(s, t0, acc[p][0]);
            acc[p][1] = fmaf(s, t1, acc[p][1]);
            acc[p][2] = fmaf(s, t2, acc[p][2]);
            acc[p][3] = fmaf(s, t3, acc[p][3]);
        }
    }

#pragma unroll
    for (int p = 0; p < P_N; p++)
#pragma unroll
        for (int r = 0; r < 4; r++)
            su[p][isub + 16 * r][w] = __half_as_ushort(__float2half_rn(acc[p][r]));
    __syncthreads();

    // Emit 1024 granules (4 per thread): kt = p*8+ic, row = (ws*4+ks)*32+ln
#pragma unroll
    for (int e = 0; e < 4; e++) {
        int gid = tid + e * 256;
        int p  = gid >> 7, f = gid & 127;
        int ks = f >> 5,  ln = f & 31;
        int g = ln >> 2,  tg = ln & 3;
        int k0 = ks * 16 + 2 * tg;
        int n0 = g, n1 = g + 8;
        uint4 u;
        u.x = (uint32_t)su[p][k0][n0]     | ((uint32_t)su[p][k0 + 1][n0] << 16);
        u.y = (uint32_t)su[p][k0 + 8][n0] | ((uint32_t)su[p][k0 + 9][n0] << 16);
        u.z = (uint32_t)su[p][k0][n1]     | ((uint32_t)su[p][k0 + 1][n1] << 16);
        u.w = (uint32_t)su[p][k0 + 8][n1] | ((uint32_t)su[p][k0 + 9][n1] << 16);
        __half* dst = g_Up + ((size_t)nb64 * N_KT + p * 8 + ic) * 4096
                      + ((size_t)(ws * 4 + ks) * 32 + ln) * 8;
        *reinterpret_cast<uint4*>(dst) = u;
    }
}

// ---------------------------------------------------------------------------
// Kernel 3: GEMM with on-the-fly A.  out[b,w] = sum_p cf[b,p] (x_b . U_p)[w].
// CTA 128m x 32n, 256 thr = 8 warps (4m x 2n), warp tile 32m x 16n.
// NIT=32: each iteration stages an 8KB B tile holding p = 2*pp and 2*pp+1
// (one wait+sync per 32 HMMA), then two 16-HMMA + cf-epilogue sub-steps.
// ---------------------------------------------------------------------------
// smem: XW [128 rows][36 words] @0 (18432) | B 3x8192 @18432 | CF @43008
#define XWOFF  0
#define BOFF   18432
#define CFOFF  43008
#define SMEM_BYTES (43008 + 4096)

__device__ __forceinline__ void issue_b2(uint32_t sb, int buf, int pbase, int ic,
                                         int nb64, int h, int tid) {
    const int ws2 = tid >> 7, ks = (tid >> 5) & 3, ln = tid & 31;
    const uint32_t off_in  = ((2 * h + ws2) * 4 + ks) * 512 + ln * 16;
    const uint32_t off_out = (ws2 * 4 + ks) * 512 + ln * 16;
#pragma unroll
    for (int q = 0; q < 2; q++) {
        const char* src = (const char*)(g_Up +
            ((size_t)nb64 * N_KT + (pbase + q) * 8 + ic) * 4096) + off_in;
        uint32_t dst = sb + BOFF + buf * 8192 + q * 4096 + off_out;
        CP_ASYNC16(dst, src);
    }
}

__global__ void __launch_bounds__(256, 2) gemm_kernel(
    const float* __restrict__ x, float* __restrict__ out)
{
    extern __shared__ char sm[];
    const uint32_t sb = smem_u32(sm);
    const int tid  = threadIdx.x;
    const int wid  = tid >> 5;
    const int lane = tid & 31;
    const int wm   = wid & 3;
    const int wn   = wid >> 2;
    const int g    = lane >> 2;
    const int tg   = lane & 3;
    const int nb32 = blockIdx.x;
    const int nb64 = nb32 >> 1;
    const int h    = nb32 & 1;
    const int mb = blockIdx.y;
    const int m0 = mb * 128;

    uint32_t* XW = reinterpret_cast<uint32_t*>(sm + XWOFF);
    float*    CF = reinterpret_cast<float*>(sm + CFOFF);

    if (tid < 128) {
        float tmin = __int_as_float(g_tmin_i);
        float tmax = __int_as_float(g_tmax_i);
        float c0 = 0.5f * (tmin + tmax);
        float hh = 0.5f * (tmax - tmin) + 1e-6f;
        float t = (g_theta[m0 + tid] - c0) / hh;
        float num[P_N];
        float S = 0.f;
        int hit = -1;
#pragma unroll
        for (int p = 0; p < P_N; p++) {
            float d = t - c_tp[p];
            if (fabsf(d) < 1e-7f) hit = p;
            num[p] = c_wp[p] / d;
            S += num[p];
        }
        if (hit >= 0) {
#pragma unroll
            for (int p = 0; p < P_N; p++) CF[tid * P_N + p] = (p == hit) ? 1.f : 0.f;
        } else {
            float inv = 1.f / S;
#pragma unroll
            for (int p = 0; p < P_N; p++) CF[tid * P_N + p] = num[p] * inv;
        }
    }

    float O[2][2][4];
#pragma unroll
    for (int i = 0; i < 2; i++)
#pragma unroll
        for (int j = 0; j < 2; j++)
#pragma unroll
            for (int r = 0; r < 4; r++) O[i][j][r] = 0.f;

    issue_b2(sb, 0, 0, 0, nb64, h, tid);
    CP_COMMIT();
    issue_b2(sb, 1, 2, 0, nb64, h, tid);
    CP_COMMIT();

    uint32_t A[4][2][4];

    for (int it = 0; it < NIT; it++) {
        const int pp = it & 3;

        CP_WAIT1();
        __syncthreads();

        if (pp == 0) {
            const float* xp = x + (size_t)m0 * D_DIM + (it >> 2) * 64;
#pragma unroll
            for (int e = 0; e < 8; e++) {
                int id = tid + e * 256;
                int m = id >> 4, q = id & 15;
                float4 v = *reinterpret_cast<const float4*>(xp + (size_t)m * D_DIM + q * 4);
                uint2 u = make_uint2(pack_h2(v.x, v.y), pack_h2(v.z, v.w));
                *reinterpret_cast<uint2*>(XW + m * 36 + q * 2) = u;
            }
            __syncthreads();
#pragma unroll
            for (int ks = 0; ks < 4; ks++) {
#pragma unroll
                for (int i = 0; i < 2; i++) {
                    int m = wm * 32 + i * 16 + g;
                    int k = ks * 8 + tg;
                    A[ks][i][0] = XW[m * 36 + k];
                    A[ks][i][1] = XW[(m + 8) * 36 + k];
                    A[ks][i][2] = XW[m * 36 + k + 4];
                    A[ks][i][3] = XW[(m + 8) * 36 + k + 4];
                }
            }
        }

        if (it + 2 < NIT)
            issue_b2(sb, (it + 2) % 3, 2 * ((it + 2) & 3), (it + 2) >> 2, nb64, h, tid);
        CP_COMMIT();

#pragma unroll
        for (int q = 0; q < 2; q++) {
            const int p = 2 * pp + q;
            const char* Bb = sm + BOFF + (it % 3) * 8192 + q * 4096
                             + wn * 2048 + lane * 16;

            float P[2][2][4];
#pragma unroll
            for (int i = 0; i < 2; i++)
#pragma unroll
                for (int j = 0; j < 2; j++)
#pragma unroll
                    for (int r = 0; r < 4; r++) P[i][j][r] = 0.f;

#pragma unroll
            for (int ks = 0; ks < 4; ks++) {
                uint4 bv = *reinterpret_cast<const uint4*>(Bb + ks * 512);
                uint32_t b[2][2];
                b[0][0] = bv.x; b[0][1] = bv.y;
                b[1][0] = bv.z; b[1][1] = bv.w;
#pragma unroll
                for (int i = 0; i < 2; i++)
#pragma unroll
                    for (int j = 0; j < 2; j++)
                        mma_f16(P[i][j], A[ks][i], b[j]);
            }

#pragma unroll
            for (int i = 0; i < 2; i++) {
                int r0 = wm * 32 + i * 16 + g;
                float d0 = CF[r0 * P_N + p];
                float d1 = CF[(r0 + 8) * P_N + p];
#pragma unroll
                for (int j = 0; j < 2; j++) {
                    O[i][j][0] = fmaf(d0, P[i][j][0], O[i][j][0]);
                    O[i][j][1] = fmaf(d0, P[i][j][1], O[i][j][1]);
                    O[i][j][2] = fmaf(d1, P[i][j][2], O[i][j][2]);
                    O[i][j][3] = fmaf(d1, P[i][j][3], O[i][j][3]);
                }
            }
        }
    }

#pragma unroll
    for (int i = 0; i < 2; i++) {
        int r0 = m0 + wm * 32 + i * 16 + g;
#pragma unroll
        for (int j = 0; j < 2; j++) {
            int col = nb32 * 32 + wn * 16 + j * 8 + 2 * tg;
            float2 v0 = make_float2(O[i][j][0], O[i][j][1]);
            float2 v1 = make_float2(O[i][j][2], O[i][j][3]);
            *reinterpret_cast<float2*>(out + (size_t)r0 * W_DIM + col)       = v0;
            *reinterpret_cast<float2*>(out + (size_t)(r0 + 8) * W_DIM + col) = v1;
        }
    }
}

// ---------------------------------------------------------------------------
extern "C" void kernel_launch(void* const* d_in, const int* in_sizes, int n_in,
                              void* d_out, int out_size)
{
    const float* x   = (const float*)d_in[0];
    const float* ray = (const float*)d_in[1];
    const float* w_i = (const float*)d_in[2];
    const float* b_i = (const float*)d_in[3];
    const float* a_i = (const float*)d_in[4];
    const float* T   = (const float*)d_in[5];
    const int*   idx = (const int*)d_in[6];
    float* out = (float*)d_out;

    cudaFuncSetAttribute(gemm_kernel,
                         cudaFuncAttributeMaxDynamicSharedMemorySize, SMEM_BYTES);

    theta_kernel<<<B_ROWS / 8, 256>>>(x, ray, w_i, b_i, a_i, idx);
    ubuild_kernel<<<dim3(8, 32), 256>>>(T);
    gemm_kernel<<<dim3(16, 16), 256, SMEM_BYTES>>>(x, out);
}